// round 10
// baseline (speedup 1.0000x reference)
#include <cuda_runtime.h>
#include <math.h>

// ClusteredAttention: b=4, l=4096, d=64 fp32, labels in [0,8).
// Counting-sort by label (coalesced staged labels, register histogram) ->
// perm/slab/block-table; gather K/V cluster-contiguous; flash-attend
// cluster-aligned 64-query blocks (256 thr, 4x4 tiles, fma.rn.f32x2 paired
// along the key axis so B operands are natural LDS.64 pairs, scale folded
// into Q). Time-query split-softmax absorbed into spare grid slots; combine
// fused into the last chunk block via threadfence+atomic counter.

#define LSEQ 4096
#define LM1  4095
#define HD   64
#define BM   64
#define BN   64
#define PADQ 66
#define NTHREADS 256
#define MAXB 4
#define MAXBLK 72
#define TQ_CHUNKS 256
#define TQ_NCH    (LSEQ / TQ_CHUNKS)   // 16
#define GRIDX     (MAXBLK + TQ_NCH)    // 88

__device__ float g_Ks[MAXB * LSEQ * HD];
__device__ float g_Vs[MAXB * LSEQ * HD];
__device__ int   g_perm[MAXB * LSEQ];
__device__ int   g_slab[MAXB * LSEQ];
__device__ int4  g_btab[MAXB * MAXBLK];
__device__ int   g_nblk[MAXB];
__device__ float g_tq[MAXB * TQ_NCH * (HD + 2)];
__device__ int   g_tqcnt[MAXB];

typedef unsigned long long u64t;

__device__ __forceinline__ u64t pack2(float lo, float hi) {
    u64t r;
    asm("mov.b64 %0, {%1, %2};" : "=l"(r) : "f"(lo), "f"(hi));
    return r;
}
__device__ __forceinline__ void unpack2(u64t v, float& lo, float& hi) {
    asm("mov.b64 {%0, %1}, %2;" : "=f"(lo), "=f"(hi) : "l"(v));
}
__device__ __forceinline__ u64t ffma2(u64t a, u64t b, u64t c) {
    u64t d;
    asm("fma.rn.f32x2 %0, %1, %2, %3;" : "=l"(d) : "l"(a), "l"(b), "l"(c));
    return d;
}
__device__ __forceinline__ u64t fmul2(u64t a, u64t b) {
    u64t d;
    asm("mul.rn.f32x2 %0, %1, %2;" : "=l"(d) : "l"(a), "l"(b));
    return d;
}

// ---------------------------------------------------------------------------
// Kernel A: counting sort. Labels staged coalesced through shared; histogram
// and run-counts fully unrolled into registers (no local-memory arrays).
// ---------------------------------------------------------------------------
__global__ void sort_kernel(const int* __restrict__ lab32)
{
    __shared__ int slabs[LSEQ];        // staged labels (LM1 used)
    __shared__ int cnt[8][256];
    __shared__ int ex[8][256];
    __shared__ int tot[8];
    __shared__ int segstart[8];
    __shared__ int sh_is64;

    const int b = blockIdx.x;
    const int tid = threadIdx.x;

    if (tid < 32) {
        int nz = (lab32[2 * tid + 1] != 0) ? 1 : 0;
        unsigned any = __ballot_sync(0xffffffffu, nz);
        if (tid == 0) { sh_is64 = (any == 0u); g_tqcnt[b] = 0; }
    }
    __syncthreads();
    const int is64 = sh_is64;
    const int labbase = b * LM1;

    // coalesced staging
    for (int idx = tid; idx < LM1; idx += NTHREADS)
        slabs[idx] = lab32[is64 ? 2 * (labbase + idx) : (labbase + idx)];
    __syncthreads();

    // per-thread 16 labels + register histogram
    int mylab[16];
    int lh[8] = {0, 0, 0, 0, 0, 0, 0, 0};
    #pragma unroll
    for (int k = 0; k < 16; k++) {
        int i = tid * 16 + k;
        int l = (i < LM1) ? slabs[i] : -1;
        mylab[k] = l;
        #pragma unroll
        for (int c = 0; c < 8; c++) lh[c] += (l == c);
    }
    #pragma unroll
    for (int l = 0; l < 8; l++) cnt[l][tid] = lh[l];
    __syncthreads();

    {
        int w = tid >> 5, lane = tid & 31;
        int carry = 0;
        for (int c = 0; c < 8; c++) {
            int t = c * 32 + lane;
            int v = cnt[w][t];
            int x = v;
            #pragma unroll
            for (int o = 1; o < 32; o <<= 1) {
                int y = __shfl_up_sync(0xffffffffu, x, o);
                if (lane >= o) x += y;
            }
            ex[w][t] = carry + x - v;
            carry += __shfl_sync(0xffffffffu, x, 31);
        }
        if (lane == 0) tot[w] = carry;
    }
    __syncthreads();

    if (tid == 0) {
        int s = 0;
        int nb = 0;
        #pragma unroll
        for (int l = 0; l < 8; l++) {
            segstart[l] = s;
            int e = s + tot[l];
            int kb = s & ~(BN - 1);
            int ke = min((e + BN - 1) & ~(BN - 1), LSEQ);
            for (int q0 = s; q0 < e; q0 += BM) {
                g_btab[b * MAXBLK + nb] = make_int4(q0, e, kb, ke);
                nb++;
            }
            s = e;
        }
        g_nblk[b] = nb;
        g_perm[b * LSEQ + LM1] = LM1;
        g_slab[b * LSEQ + LM1] = -2;
    }
    __syncthreads();

    // scatter: run-count recomputed with unrolled compares (registers only)
    #pragma unroll
    for (int k = 0; k < 16; k++) {
        int l = mylab[k];
        if (l >= 0) {
            int run = 0;
            #pragma unroll
            for (int k2 = 0; k2 < 16; k2++)
                if (k2 < k) run += (mylab[k2] == l);
            int pos = segstart[l] + ex[l][tid] + run;
            int i = tid * 16 + k;
            g_perm[b * LSEQ + pos] = i;
            g_slab[b * LSEQ + pos] = l;
        }
    }
}

// ---------------------------------------------------------------------------
// Kernel B: gather K/V rows into sorted order.
// ---------------------------------------------------------------------------
__global__ void gather_kernel(const float* __restrict__ K,
                              const float* __restrict__ V)
{
    int idx = blockIdx.x * blockDim.x + threadIdx.x;
    int r = idx >> 4;
    int c = idx & 15;
    int b = r >> 12;
    int src = g_perm[r];
    long long so = ((long long)(b << 12) + src) * 16 + c;
    ((float4*)g_Ks)[r * 16 + c] = ((const float4*)K)[so];
    ((float4*)g_Vs)[r * 16 + c] = ((const float4*)V)[so];
}

// ---------------------------------------------------------------------------
// Kernel C: main kernel, 256 threads.
// ---------------------------------------------------------------------------
__global__ __launch_bounds__(NTHREADS, 2)
void clustered_attn_kernel(const float* __restrict__ Q,
                           const float* __restrict__ K,
                           const float* __restrict__ V,
                           float* __restrict__ Out)
{
    extern __shared__ float sm[];

    const int b    = blockIdx.y;
    const int slot = blockIdx.x;
    const int tid  = threadIdx.x;
    const int nblk = g_nblk[b];
    const long long bbase = (long long)b * LSEQ;
    const float scale = 0.125f;

    // ===================== time-query chunk path =====================
    if (slot >= nblk) {
        const int c = slot - nblk;
        if (c >= TQ_NCH) return;

        float* q    = sm;
        float* p    = sm + 64;
        float* red  = sm + 320;
        float* vacc = sm + 336;
        __shared__ int amlast;

        if (tid < HD) q[tid] = Q[(bbase + LM1) * HD + tid];
        __syncthreads();

        const int j = c * TQ_CHUNKS + tid;
        const float* kr = K + (bbase + j) * HD;
        float dot = 0.0f;
        #pragma unroll
        for (int d = 0; d < HD; d += 4) {
            float4 k4 = *reinterpret_cast<const float4*>(kr + d);
            dot += q[d] * k4.x + q[d + 1] * k4.y + q[d + 2] * k4.z + q[d + 3] * k4.w;
        }
        dot *= scale;

        float m = dot;
        #pragma unroll
        for (int o = 16; o >= 1; o >>= 1)
            m = fmaxf(m, __shfl_xor_sync(0xffffffffu, m, o));
        if ((tid & 31) == 0) red[tid >> 5] = m;
        __syncthreads();
        m = red[0];
        #pragma unroll
        for (int w = 1; w < 8; w++) m = fmaxf(m, red[w]);

        float pv = __expf(dot - m);
        p[tid] = pv;

        float s = pv;
        #pragma unroll
        for (int o = 16; o >= 1; o >>= 1)
            s += __shfl_xor_sync(0xffffffffu, s, o);
        if ((tid & 31) == 0) red[8 + (tid >> 5)] = s;
        __syncthreads();
        s = red[8];
        #pragma unroll
        for (int w = 1; w < 8; w++) s += red[8 + w];

        const int d = tid & 63, h = tid >> 6;
        float a = 0.0f;
        #pragma unroll 8
        for (int jj = h * 64; jj < h * 64 + 64; jj++)
            a += p[jj] * V[(bbase + c * TQ_CHUNKS + jj) * HD + d];
        vacc[h * HD + d] = a;
        __syncthreads();

        float* out = g_tq + (b * TQ_NCH + c) * (HD + 2);
        if (tid < HD)
            out[tid] = vacc[tid] + vacc[HD + tid] + vacc[2 * HD + tid] + vacc[3 * HD + tid];
        else if (tid == HD) { out[HD] = m; out[HD + 1] = s; }
        __syncthreads();

        __threadfence();
        if (tid == 0) amlast = (atomicAdd(&g_tqcnt[b], 1) == TQ_NCH - 1);
        __syncthreads();
        if (!amlast) return;
        __threadfence();

        if (tid < HD) {
            const float* part = g_tq + b * TQ_NCH * (HD + 2);
            float M = -INFINITY;
            #pragma unroll
            for (int cc = 0; cc < TQ_NCH; cc++)
                M = fmaxf(M, part[cc * (HD + 2) + HD]);
            float stot = 0.0f, a2 = 0.0f;
            #pragma unroll
            for (int cc = 0; cc < TQ_NCH; cc++) {
                float f = __expf(part[cc * (HD + 2) + HD] - M);
                stot += part[cc * (HD + 2) + HD + 1] * f;
                a2   += part[cc * (HD + 2) + tid] * f;
            }
            Out[(bbase + LM1) * HD + tid] = a2 / stot;
        }
        return;
    }

    // ===================== attention path =====================
    float* Qt = sm;                       // [HD][PADQ] (pre-scaled by 0.125)
    float* Kt = Qt + HD * PADQ;           // [HD][PADQ]
    float* Pt = Kt + HD * PADQ;           // [BN][PADQ]
    float* Vs = Pt + BN * PADQ;           // [BN][HD]
    int*   klabs = (int*)(Vs + BN * HD);
    float* kt = (float*)(klabs + BN);
    float* vt = kt + HD;

    const int4 blk = g_btab[b * MAXBLK + slot];
    const int q0 = blk.x, qe = blk.y, kb = blk.z, ke = blk.w;

    const int tx = tid & 15;
    const int ty = tid >> 4;
    const int* perm = g_perm + b * LSEQ;
    const int* slab = g_slab + b * LSEQ;

    const float* Kb = g_Ks + b * LSEQ * HD;
    const float* Vb = g_Vs + b * LSEQ * HD;

    // ---- Q tile (transposed, pre-scaled) from original Q via perm
    {
        int r = tid >> 2, h = tid & 3;
        int rr = min(q0 + r, LM1);
        int src = perm[rr];
        const float4* qrow = reinterpret_cast<const float4*>(Q + (bbase + src) * HD) + h * 4;
        #pragma unroll
        for (int k2 = 0; k2 < 4; k2++) {
            float4 v4 = qrow[k2];
            int d = h * 16 + k2 * 4;
            Qt[(d + 0) * PADQ + r] = v4.x * scale;
            Qt[(d + 1) * PADQ + r] = v4.y * scale;
            Qt[(d + 2) * PADQ + r] = v4.z * scale;
            Qt[(d + 3) * PADQ + r] = v4.w * scale;
        }
    }
    if (tid < HD) kt[tid] = Kb[LM1 * HD + tid];
    else if (tid < 2 * HD) vt[tid - HD] = Vb[LM1 * HD + (tid - HD)];

    int qlab[4];
    #pragma unroll
    for (int i = 0; i < 4; i++) {
        int r = q0 + ty * 4 + i;
        qlab[i] = (r < qe) ? slab[r] : -3;
    }

    float mrow[4], lrow[4];
    u64t acc2[4][2];                 // row i, key-pair jp: lanes (j=2jp, 2jp+1)
    #pragma unroll
    for (int i = 0; i < 4; i++) {
        mrow[i] = -INFINITY;
        lrow[i] = 0.0f;
        acc2[i][0] = 0ull;
        acc2[i][1] = 0ull;
    }

    for (int n0 = kb; n0 < ke; n0 += BN) {
        __syncthreads();

        #pragma unroll
        for (int idx = tid; idx < BN * HD; idx += NTHREADS) {
            int n = idx >> 6, d = idx & 63;
            Kt[d * PADQ + n] = Kb[(n0 + n) * HD + d];
            Vs[n * HD + d]  = Vb[(n0 + n) * HD + d];
        }
        if (tid < BN) klabs[tid] = slab[n0 + tid];
        __syncthreads();

        // ---- S = Q K^T : f32x2 with lanes along key pairs (B loads natural)
        u64t s2[4][2];
        #pragma unroll
        for (int i = 0; i < 4; i++) { s2[i][0] = 0ull; s2[i][1] = 0ull; }

        #pragma unroll 4
        for (int d = 0; d < HD; d++) {
            u64t a01 = *reinterpret_cast<const u64t*>(&Qt[d * PADQ + 4 * ty]);
            u64t a23 = *reinterpret_cast<const u64t*>(&Qt[d * PADQ + 4 * ty + 2]);
            u64t b01 = *reinterpret_cast<const u64t*>(&Kt[d * PADQ + 4 * tx]);
            u64t b23 = *reinterpret_cast<const u64t*>(&Kt[d * PADQ + 4 * tx + 2]);
            float a0, a1, a2, a3;
            unpack2(a01, a0, a1);
            unpack2(a23, a2, a3);
            u64t A0 = pack2(a0, a0), A1 = pack2(a1, a1);
            u64t A2 = pack2(a2, a2), A3 = pack2(a3, a3);
            s2[0][0] = ffma2(A0, b01, s2[0][0]);
            s2[0][1] = ffma2(A0, b23, s2[0][1]);
            s2[1][0] = ffma2(A1, b01, s2[1][0]);
            s2[1][1] = ffma2(A1, b23, s2[1][1]);
            s2[2][0] = ffma2(A2, b01, s2[2][0]);
            s2[2][1] = ffma2(A2, b23, s2[2][1]);
            s2[3][0] = ffma2(A3, b01, s2[3][0]);
            s2[3][1] = ffma2(A3, b23, s2[3][1]);
        }

        // ---- unpack (Q pre-scaled, so s is already scaled)
        float s[4][4];
        #pragma unroll
        for (int i = 0; i < 4; i++) {
            unpack2(s2[i][0], s[i][0], s[i][1]);
            unpack2(s2[i][1], s[i][2], s[i][3]);
        }

        int klj[4];
        #pragma unroll
        for (int j = 0; j < 4; j++) klj[j] = klabs[4 * tx + j];

        #pragma unroll
        for (int i = 0; i < 4; i++)
            #pragma unroll
            for (int j = 0; j < 4; j++)
                s[i][j] = (qlab[i] == klj[j]) ? s[i][j] : -INFINITY;

        float fi[4];
        #pragma unroll
        for (int i = 0; i < 4; i++) {
            float tm = fmaxf(fmaxf(s[i][0], s[i][1]), fmaxf(s[i][2], s[i][3]));
            #pragma unroll
            for (int o = 8; o >= 1; o >>= 1)
                tm = fmaxf(tm, __shfl_xor_sync(0xffffffffu, tm, o));

            float newm = fmaxf(mrow[i], tm);
            float mref = (newm == -INFINITY) ? 0.0f : newm;
            fi[i] = __expf(mrow[i] - mref);

            float rs = 0.0f;
            #pragma unroll
            for (int j = 0; j < 4; j++) {
                float p = __expf(s[i][j] - mref);
                s[i][j] = p;
                rs += p;
            }
            #pragma unroll
            for (int o = 8; o >= 1; o >>= 1)
                rs += __shfl_xor_sync(0xffffffffu, rs, o);

            lrow[i] = lrow[i] * fi[i] + rs;
            mrow[i] = newm;
        }

        #pragma unroll
        for (int i = 0; i < 4; i++) {
            u64t F = pack2(fi[i], fi[i]);
            acc2[i][0] = fmul2(acc2[i][0], F);
            acc2[i][1] = fmul2(acc2[i][1], F);
        }

        // ---- stage P^T, then O += P @ V (f32x2, lanes along out-dim pairs)
        #pragma unroll
        for (int i = 0; i < 4; i++)
            #pragma unroll
            for (int j = 0; j < 4; j++)
                Pt[(4 * tx + j) * PADQ + (4 * ty + i)] = s[i][j];
        __syncthreads();

        #pragma unroll 4
        for (int n = 0; n < BN; n++) {
            u64t a01 = *reinterpret_cast<const u64t*>(&Pt[n * PADQ + 4 * ty]);
            u64t a23 = *reinterpret_cast<const u64t*>(&Pt[n * PADQ + 4 * ty + 2]);
            u64t v01 = *reinterpret_cast<const u64t*>(&Vs[n * HD + 4 * tx]);
            u64t v23 = *reinterpret_cast<const u64t*>(&Vs[n * HD + 4 * tx + 2]);
            float a0, a1, a2, a3;
            unpack2(a01, a0, a1);
            unpack2(a23, a2, a3);
            u64t A0 = pack2(a0, a0), A1 = pack2(a1, a1);
            u64t A2 = pack2(a2, a2), A3 = pack2(a3, a3);
            acc2[0][0] = ffma2(A0, v01, acc2[0][0]);
            acc2[0][1] = ffma2(A0, v23, acc2[0][1]);
            acc2[1][0] = ffma2(A1, v01, acc2[1][0]);
            acc2[1][1] = ffma2(A1, v23, acc2[1][1]);
            acc2[2][0] = ffma2(A2, v01, acc2[2][0]);
            acc2[2][1] = ffma2(A2, v23, acc2[2][1]);
            acc2[3][0] = ffma2(A3, v01, acc2[3][0]);
            acc2[3][1] = ffma2(A3, v23, acc2[3][1]);
        }
    }

    // ---- unpack accumulators
    float acc[4][4];
    #pragma unroll
    for (int i = 0; i < 4; i++) {
        unpack2(acc2[i][0], acc[i][0], acc[i][1]);
        unpack2(acc2[i][1], acc[i][2], acc[i][3]);
    }

    // ---- time key column (Qt pre-scaled -> no extra scale)
    #pragma unroll
    for (int i = 0; i < 4; i++) {
        float part = 0.0f;
        #pragma unroll
        for (int jj = 0; jj < 4; jj++)
            part += Qt[(4 * tx + jj) * PADQ + (4 * ty + i)] * kt[4 * tx + jj];
        #pragma unroll
        for (int o = 8; o >= 1; o >>= 1)
            part += __shfl_xor_sync(0xffffffffu, part, o);
        float st = part;

        float newm = fmaxf(mrow[i], st);
        float f = __expf(mrow[i] - newm);
        float p = __expf(st - newm);
        lrow[i] = lrow[i] * f + p;
        mrow[i] = newm;
        #pragma unroll
        for (int j = 0; j < 4; j++)
            acc[i][j] = acc[i][j] * f + p * vt[4 * tx + j];
    }

    // ---- epilogue: normalize + scatter
    #pragma unroll
    for (int i = 0; i < 4; i++) {
        int r = q0 + 4 * ty + i;
        if (r < qe) {
            float inv = 1.0f / lrow[i];
            int orig = perm[r];
            float4 o4;
            o4.x = acc[i][0] * inv;
            o4.y = acc[i][1] * inv;
            o4.z = acc[i][2] * inv;
            o4.w = acc[i][3] * inv;
            *reinterpret_cast<float4*>(&Out[(bbase + orig) * HD + 4 * tx]) = o4;
        }
    }
}

// ---------------------------------------------------------------------------
extern "C" void kernel_launch(void* const* d_in, const int* in_sizes, int n_in,
                              void* d_out, int out_size)
{
    const float* Q = (const float*)d_in[0];
    const float* K = (const float*)d_in[1];
    const float* V = (const float*)d_in[2];
    const int* lab = (const int*)d_in[3];
    float* Out = (float*)d_out;

    const int B = in_sizes[0] / (LSEQ * HD);

    sort_kernel<<<B, 256>>>(lab);
    gather_kernel<<<B * 256, 256>>>(K, V);

    const int smem_bytes = (HD * PADQ * 2 + BN * PADQ + BN * HD + 2 * HD) * (int)sizeof(float)
                           + BN * (int)sizeof(int);
    cudaFuncSetAttribute(clustered_attn_kernel,
                         cudaFuncAttributeMaxDynamicSharedMemorySize, smem_bytes);
    dim3 grid(GRIDX, B);
    clustered_attn_kernel<<<grid, NTHREADS, smem_bytes>>>(Q, K, V, Out);
}

// round 11
// speedup vs baseline: 1.2296x; 1.2296x over previous
#include <cuda_runtime.h>
#include <math.h>

// ClusteredAttention: b=4, l=4096, d=64 fp32, labels in [0,8).
// Counting-sort by label -> perm/slab/block-table; gather K/V cluster-
// contiguous WITH tf32 pre-conversion; flash-attend cluster-aligned 64-query
// blocks using mma.sync.m16n8k8 TF32 tensor-core GEMMs for both S=QK^T and
// O+=PV (S staged through smem so the proven scalar mask/online-softmax path
// is unchanged). Time-query split-softmax absorbed into spare grid slots;
// combine fused into last chunk block.

#define LSEQ 4096
#define LM1  4095
#define HD   64
#define BM   64
#define BN   64
#define PADS 66
#define NTHREADS 256
#define MAXB 4
#define MAXBLK 72
#define TQ_CHUNKS 256
#define TQ_NCH    (LSEQ / TQ_CHUNKS)   // 16
#define GRIDX     (MAXBLK + TQ_NCH)    // 88

__device__ float g_Ks[MAXB * LSEQ * HD];   // tf32-rounded
__device__ float g_Vs[MAXB * LSEQ * HD];   // tf32-rounded
__device__ int   g_perm[MAXB * LSEQ];
__device__ int   g_slab[MAXB * LSEQ];
__device__ int4  g_btab[MAXB * MAXBLK];
__device__ int   g_nblk[MAXB];
__device__ float g_tq[MAXB * TQ_NCH * (HD + 2)];
__device__ int   g_tqcnt[MAXB];

__device__ __forceinline__ unsigned f2tf32(float v) {
    unsigned r;
    asm("cvt.rna.tf32.f32 %0, %1;" : "=r"(r) : "f"(v));
    return r;
}

__device__ __forceinline__ void mma_tf32(float c[4],
                                         unsigned a0, unsigned a1,
                                         unsigned a2, unsigned a3,
                                         unsigned b0, unsigned b1) {
    asm("mma.sync.aligned.m16n8k8.row.col.f32.tf32.tf32.f32 "
        "{%0,%1,%2,%3}, {%4,%5,%6,%7}, {%8,%9}, {%0,%1,%2,%3};"
        : "+f"(c[0]), "+f"(c[1]), "+f"(c[2]), "+f"(c[3])
        : "r"(a0), "r"(a1), "r"(a2), "r"(a3), "r"(b0), "r"(b1));
}

// ---------------------------------------------------------------------------
// Kernel A: counting sort (round-9 proven variant) + block table.
// ---------------------------------------------------------------------------
__global__ void sort_kernel(const int* __restrict__ lab32)
{
    __shared__ int cnt[8][256];
    __shared__ int ex[8][256];
    __shared__ int tot[8];
    __shared__ int segstart[8];
    __shared__ int sh_is64;

    const int b = blockIdx.x;
    const int tid = threadIdx.x;

    if (tid < 32) {
        int nz = (lab32[2 * tid + 1] != 0) ? 1 : 0;
        unsigned any = __ballot_sync(0xffffffffu, nz);
        if (tid == 0) { sh_is64 = (any == 0u); g_tqcnt[b] = 0; }
    }
    __syncthreads();
    const int is64 = sh_is64;
    const int labbase = b * LM1;

    int mylab[16];
    int lh[8] = {0, 0, 0, 0, 0, 0, 0, 0};
    #pragma unroll
    for (int k = 0; k < 16; k++) {
        int i = tid * 16 + k;
        int l = -1;
        if (i < LM1) {
            int gi = labbase + i;
            l = lab32[is64 ? (2 * gi) : gi];
            lh[l]++;
        }
        mylab[k] = l;
    }
    #pragma unroll
    for (int l = 0; l < 8; l++) cnt[l][tid] = lh[l];
    __syncthreads();

    {
        int w = tid >> 5, lane = tid & 31;
        int carry = 0;
        for (int c = 0; c < 8; c++) {
            int t = c * 32 + lane;
            int v = cnt[w][t];
            int x = v;
            #pragma unroll
            for (int o = 1; o < 32; o <<= 1) {
                int y = __shfl_up_sync(0xffffffffu, x, o);
                if (lane >= o) x += y;
            }
            ex[w][t] = carry + x - v;
            carry += __shfl_sync(0xffffffffu, x, 31);
        }
        if (lane == 0) tot[w] = carry;
    }
    __syncthreads();

    if (tid == 0) {
        int s = 0;
        int nb = 0;
        #pragma unroll
        for (int l = 0; l < 8; l++) {
            segstart[l] = s;
            int e = s + tot[l];
            int kb = s & ~(BN - 1);
            int ke = min((e + BN - 1) & ~(BN - 1), LSEQ);
            for (int q0 = s; q0 < e; q0 += BM) {
                g_btab[b * MAXBLK + nb] = make_int4(q0, e, kb, ke);
                nb++;
            }
            s = e;
        }
        g_nblk[b] = nb;
        g_perm[b * LSEQ + LM1] = LM1;
        g_slab[b * LSEQ + LM1] = -2;
    }
    __syncthreads();

    int run[8] = {0, 0, 0, 0, 0, 0, 0, 0};
    #pragma unroll
    for (int k = 0; k < 16; k++) {
        int l = mylab[k];
        if (l >= 0) {
            int pos = segstart[l] + ex[l][tid] + run[l]++;
            int i = tid * 16 + k;
            g_perm[b * LSEQ + pos] = i;
            g_slab[b * LSEQ + pos] = l;
        }
    }
}

// ---------------------------------------------------------------------------
// Kernel B: gather K/V rows into sorted order + tf32 pre-conversion.
// ---------------------------------------------------------------------------
__global__ void gather_kernel(const float* __restrict__ K,
                              const float* __restrict__ V)
{
    int idx = blockIdx.x * blockDim.x + threadIdx.x;
    int r = idx >> 4;
    int c = idx & 15;
    int b = r >> 12;
    int src = g_perm[r];
    long long so = ((long long)(b << 12) + src) * 16 + c;
    float4 k4 = ((const float4*)K)[so];
    float4 v4 = ((const float4*)V)[so];
    k4.x = __uint_as_float(f2tf32(k4.x));
    k4.y = __uint_as_float(f2tf32(k4.y));
    k4.z = __uint_as_float(f2tf32(k4.z));
    k4.w = __uint_as_float(f2tf32(k4.w));
    v4.x = __uint_as_float(f2tf32(v4.x));
    v4.y = __uint_as_float(f2tf32(v4.y));
    v4.z = __uint_as_float(f2tf32(v4.z));
    v4.w = __uint_as_float(f2tf32(v4.w));
    ((float4*)g_Ks)[r * 16 + c] = k4;
    ((float4*)g_Vs)[r * 16 + c] = v4;
}

// ---------------------------------------------------------------------------
// Kernel C: main kernel, 256 threads, TF32 tensor-core GEMMs.
// ---------------------------------------------------------------------------
__global__ __launch_bounds__(NTHREADS, 2)
void clustered_attn_kernel(const float* __restrict__ Q,
                           const float* __restrict__ K,
                           const float* __restrict__ V,
                           float* __restrict__ Out)
{
    extern __shared__ float sm[];

    const int b    = blockIdx.y;
    const int slot = blockIdx.x;
    const int tid  = threadIdx.x;
    const int nblk = g_nblk[b];
    const long long bbase = (long long)b * LSEQ;
    const float scale = 0.125f;

    // ===================== time-query chunk path (exact fp32) ============
    if (slot >= nblk) {
        const int c = slot - nblk;
        if (c >= TQ_NCH) return;

        float* q    = sm;
        float* p    = sm + 64;
        float* red  = sm + 320;
        float* vacc = sm + 336;
        __shared__ int amlast;

        if (tid < HD) q[tid] = Q[(bbase + LM1) * HD + tid];
        __syncthreads();

        const int j = c * TQ_CHUNKS + tid;
        const float* kr = K + (bbase + j) * HD;
        float dot = 0.0f;
        #pragma unroll
        for (int d = 0; d < HD; d += 4) {
            float4 k4 = *reinterpret_cast<const float4*>(kr + d);
            dot += q[d] * k4.x + q[d + 1] * k4.y + q[d + 2] * k4.z + q[d + 3] * k4.w;
        }
        dot *= scale;

        float m = dot;
        #pragma unroll
        for (int o = 16; o >= 1; o >>= 1)
            m = fmaxf(m, __shfl_xor_sync(0xffffffffu, m, o));
        if ((tid & 31) == 0) red[tid >> 5] = m;
        __syncthreads();
        m = red[0];
        #pragma unroll
        for (int w = 1; w < 8; w++) m = fmaxf(m, red[w]);

        float pv = __expf(dot - m);
        p[tid] = pv;

        float s = pv;
        #pragma unroll
        for (int o = 16; o >= 1; o >>= 1)
            s += __shfl_xor_sync(0xffffffffu, s, o);
        if ((tid & 31) == 0) red[8 + (tid >> 5)] = s;
        __syncthreads();
        s = red[8];
        #pragma unroll
        for (int w = 1; w < 8; w++) s += red[8 + w];

        const int d = tid & 63, h = tid >> 6;
        float a = 0.0f;
        #pragma unroll 8
        for (int jj = h * 64; jj < h * 64 + 64; jj++)
            a += p[jj] * V[(bbase + c * TQ_CHUNKS + jj) * HD + d];
        vacc[h * HD + d] = a;
        __syncthreads();

        float* out = g_tq + (b * TQ_NCH + c) * (HD + 2);
        if (tid < HD)
            out[tid] = vacc[tid] + vacc[HD + tid] + vacc[2 * HD + tid] + vacc[3 * HD + tid];
        else if (tid == HD) { out[HD] = m; out[HD + 1] = s; }
        __syncthreads();

        __threadfence();
        if (tid == 0) amlast = (atomicAdd(&g_tqcnt[b], 1) == TQ_NCH - 1);
        __syncthreads();
        if (!amlast) return;
        __threadfence();

        if (tid < HD) {
            const float* part = g_tq + b * TQ_NCH * (HD + 2);
            float M = -INFINITY;
            #pragma unroll
            for (int cc = 0; cc < TQ_NCH; cc++)
                M = fmaxf(M, part[cc * (HD + 2) + HD]);
            float stot = 0.0f, a2 = 0.0f;
            #pragma unroll
            for (int cc = 0; cc < TQ_NCH; cc++) {
                float f = __expf(part[cc * (HD + 2) + HD] - M);
                stot += part[cc * (HD + 2) + HD + 1] * f;
                a2   += part[cc * (HD + 2) + tid] * f;
            }
            Out[(bbase + LM1) * HD + tid] = a2 / stot;
        }
        return;
    }

    // ===================== attention path =====================
    float* Qs = sm;                      // [64][PADS] row-major, pre-scaled tf32
    float* Ks = Qs + 64 * PADS;          // [64][PADS] tf32
    float* Vs = Ks + 64 * PADS;          // [64][PADS] tf32
    float* St = Vs + 64 * PADS;          // [64][PADS] scores / probs
    float* kt = St + 64 * PADS;          // [64] exact time key
    float* vt = kt + 64;                 // [64] exact time value
    float* frow_s = vt + 64;             // [64] per-row rescale
    float* ft_s   = frow_s + 64;
    float* pt_s   = ft_s + 64;
    float* li_s   = pt_s + 64;
    int*   klabs  = (int*)(li_s + 64);   // [64]

    const unsigned* Qu = (const unsigned*)Qs;
    const unsigned* Ku = (const unsigned*)Ks;
    const unsigned* Vu = (const unsigned*)Vs;
    const unsigned* Su = (const unsigned*)St;

    const int4 blk = g_btab[b * MAXBLK + slot];
    const int q0 = blk.x, qe = blk.y, kb = blk.z, ke = blk.w;

    const int tx = tid & 15;
    const int ty = tid >> 4;
    const int lane = tid & 31;
    const int warp = tid >> 5;
    const int mw = 16 * (warp >> 1);     // warp's m-slab (0/16/32/48)
    const int nw = 32 * (warp & 1);      // warp's n-half (0/32)
    const int gid = lane >> 2;
    const int tig = lane & 3;
    const int rA0 = (mw + gid) * PADS;
    const int rA1 = (mw + gid + 8) * PADS;

    const int* perm = g_perm + b * LSEQ;
    const int* slab = g_slab + b * LSEQ;
    const float* Kb = g_Ks + b * LSEQ * HD;
    const float* Vb = g_Vs + b * LSEQ * HD;

    // ---- stage Q (row-major, scaled, tf32) + exact time K/V
    #pragma unroll
    for (int idx = tid; idx < BM * HD; idx += NTHREADS) {
        int m = idx >> 6, d = idx & 63;
        int src = perm[min(q0 + m, LM1)];
        float v = Q[(bbase + src) * HD + d] * scale;
        Qs[m * PADS + d] = __uint_as_float(f2tf32(v));
    }
    if (tid < HD) kt[tid] = K[(bbase + LM1) * HD + tid];
    else if (tid < 2 * HD) vt[tid - HD] = V[(bbase + LM1) * HD + (tid - HD)];

    int qlab[4];
    #pragma unroll
    for (int i = 0; i < 4; i++) {
        int r = q0 + ty * 4 + i;
        qlab[i] = (r < qe) ? slab[r] : -3;
    }

    float mrow[4], lrow[4];
    #pragma unroll
    for (int i = 0; i < 4; i++) { mrow[i] = -INFINITY; lrow[i] = 0.0f; }

    float oc[4][4];                      // O frags: 4 n-groups x 4 regs
    #pragma unroll
    for (int ng = 0; ng < 4; ng++)
        #pragma unroll
        for (int r = 0; r < 4; r++) oc[ng][r] = 0.0f;

    for (int n0 = kb; n0 < ke; n0 += BN) {
        __syncthreads();   // prev PV reads done; Q staging done on iter 0

        // ---- stage K/V tiles (row-major float2 copy; already tf32)
        #pragma unroll
        for (int idx = tid; idx < BN * 32; idx += NTHREADS) {
            int n = idx >> 5, c = (idx & 31) * 2;
            *(float2*)&Ks[n * PADS + c] = *(const float2*)&Kb[(n0 + n) * HD + c];
            *(float2*)&Vs[n * PADS + c] = *(const float2*)&Vb[(n0 + n) * HD + c];
        }
        if (tid < BN) klabs[tid] = slab[n0 + tid];
        __syncthreads();

        // ---- S = Q K^T via tensor cores (warp: 16m x 32n slab)
        float sc[4][4];
        #pragma unroll
        for (int ng = 0; ng < 4; ng++)
            #pragma unroll
            for (int r = 0; r < 4; r++) sc[ng][r] = 0.0f;

        #pragma unroll
        for (int kg = 0; kg < 8; kg++) {
            int k0 = kg * 8;
            unsigned a0 = Qu[rA0 + k0 + tig];
            unsigned a1 = Qu[rA1 + k0 + tig];
            unsigned a2 = Qu[rA0 + k0 + tig + 4];
            unsigned a3 = Qu[rA1 + k0 + tig + 4];
            #pragma unroll
            for (int ng = 0; ng < 4; ng++) {
                int nb = (nw + 8 * ng + gid) * PADS + k0 + tig;
                mma_tf32(sc[ng], a0, a1, a2, a3, Ku[nb], Ku[nb + 4]);
            }
        }
        #pragma unroll
        for (int ng = 0; ng < 4; ng++) {
            int cbase = nw + 8 * ng + 2 * tig;
            *(float2*)&St[rA0 + cbase] = make_float2(sc[ng][0], sc[ng][1]);
            *(float2*)&St[rA1 + cbase] = make_float2(sc[ng][2], sc[ng][3]);
        }
        __syncthreads();

        // ---- mask + online softmax (proven scalar path, on smem S)
        int klj[4];
        #pragma unroll
        for (int j = 0; j < 4; j++) klj[j] = klabs[4 * tx + j];

        #pragma unroll
        for (int i = 0; i < 4; i++) {
            int rbase = (4 * ty + i) * PADS + 4 * tx;
            float2 lo = *(const float2*)&St[rbase];
            float2 hi = *(const float2*)&St[rbase + 2];
            float s0 = (qlab[i] == klj[0]) ? lo.x : -INFINITY;
            float s1 = (qlab[i] == klj[1]) ? lo.y : -INFINITY;
            float s2 = (qlab[i] == klj[2]) ? hi.x : -INFINITY;
            float s3 = (qlab[i] == klj[3]) ? hi.y : -INFINITY;

            float tm = fmaxf(fmaxf(s0, s1), fmaxf(s2, s3));
            #pragma unroll
            for (int o = 8; o >= 1; o >>= 1)
                tm = fmaxf(tm, __shfl_xor_sync(0xffffffffu, tm, o));

            float newm = fmaxf(mrow[i], tm);
            float mref = (newm == -INFINITY) ? 0.0f : newm;
            float fi = __expf(mrow[i] - mref);

            float p0 = __expf(s0 - mref);
            float p1 = __expf(s1 - mref);
            float p2 = __expf(s2 - mref);
            float p3 = __expf(s3 - mref);
            float rs = (p0 + p1) + (p2 + p3);
            #pragma unroll
            for (int o = 8; o >= 1; o >>= 1)
                rs += __shfl_xor_sync(0xffffffffu, rs, o);

            lrow[i] = lrow[i] * fi + rs;
            mrow[i] = newm;

            // write P (tf32) back in place
            *(float2*)&St[rbase] = make_float2(__uint_as_float(f2tf32(p0)),
                                               __uint_as_float(f2tf32(p1)));
            *(float2*)&St[rbase + 2] = make_float2(__uint_as_float(f2tf32(p2)),
                                                   __uint_as_float(f2tf32(p3)));
            if (tx == 0) frow_s[4 * ty + i] = fi;
        }
        __syncthreads();

        // ---- O = O*f + P V via tensor cores
        {
            float f0 = frow_s[mw + gid];
            float f1 = frow_s[mw + gid + 8];
            #pragma unroll
            for (int ng = 0; ng < 4; ng++) {
                oc[ng][0] *= f0; oc[ng][1] *= f0;
                oc[ng][2] *= f1; oc[ng][3] *= f1;
            }
        }
        #pragma unroll
        for (int kg = 0; kg < 8; kg++) {
            int k0 = kg * 8;
            unsigned a0 = Su[rA0 + k0 + tig];
            unsigned a1 = Su[rA1 + k0 + tig];
            unsigned a2 = Su[rA0 + k0 + tig + 4];
            unsigned a3 = Su[rA1 + k0 + tig + 4];
            #pragma unroll
            for (int ng = 0; ng < 4; ng++) {
                int vb = (k0 + tig) * PADS + nw + 8 * ng + gid;
                mma_tf32(oc[ng], a0, a1, a2, a3, Vu[vb], Vu[vb + 4 * PADS]);
            }
        }
    }

    // ---- time key column (exact fp32): per-row owners compute f,p,1/l
    #pragma unroll
    for (int i = 0; i < 4; i++) {
        int row = 4 * ty + i;
        float part = 0.0f;
        #pragma unroll
        for (int jj = 0; jj < 4; jj++)
            part += Qs[row * PADS + 4 * tx + jj] * kt[4 * tx + jj];
        #pragma unroll
        for (int o = 8; o >= 1; o >>= 1)
            part += __shfl_xor_sync(0xffffffffu, part, o);
        float st = part;   // Q pre-scaled

        float newm = fmaxf(mrow[i], st);
        float f = __expf(mrow[i] - newm);
        float p = __expf(st - newm);
        lrow[i] = lrow[i] * f + p;
        mrow[i] = newm;
        if (tx == 0) {
            ft_s[row] = f;
            pt_s[row] = p;
            li_s[row] = 1.0f / lrow[i];
        }
    }
    __syncthreads();

    // ---- epilogue on O frags: time-key add, normalize, scatter
    {
        float f0 = ft_s[mw + gid],     p0 = pt_s[mw + gid],     i0 = li_s[mw + gid];
        float f1 = ft_s[mw + gid + 8], p1 = pt_s[mw + gid + 8], i1 = li_s[mw + gid + 8];
        int r0 = q0 + mw + gid;
        int r1 = r0 + 8;
        bool good0 = r0 < qe, good1 = r1 < qe;
        long long o0 = good0 ? (bbase + perm[r0]) * HD : 0;
        long long o1 = good1 ? (bbase + perm[r1]) * HD : 0;

        #pragma unroll
        for (int ng = 0; ng < 4; ng++) {
            int col = nw + 8 * ng + 2 * tig;
            float x0 = (oc[ng][0] * f0 + p0 * vt[col])     * i0;
            float x1 = (oc[ng][1] * f0 + p0 * vt[col + 1]) * i0;
            float x2 = (oc[ng][2] * f1 + p1 * vt[col])     * i1;
            float x3 = (oc[ng][3] * f1 + p1 * vt[col + 1]) * i1;
            if (good0) *(float2*)&Out[o0 + col] = make_float2(x0, x1);
            if (good1) *(float2*)&Out[o1 + col] = make_float2(x2, x3);
        }
    }
}

// ---------------------------------------------------------------------------
extern "C" void kernel_launch(void* const* d_in, const int* in_sizes, int n_in,
                              void* d_out, int out_size)
{
    const float* Q = (const float*)d_in[0];
    const float* K = (const float*)d_in[1];
    const float* V = (const float*)d_in[2];
    const int* lab = (const int*)d_in[3];
    float* Out = (float*)d_out;

    const int B = in_sizes[0] / (LSEQ * HD);

    sort_kernel<<<B, 256>>>(lab);
    gather_kernel<<<B * 256, 256>>>(K, V);

    const int smem_bytes = (4 * 64 * PADS + 7 * 64) * (int)sizeof(float)
                           + 64 * (int)sizeof(int);
    cudaFuncSetAttribute(clustered_attn_kernel,
                         cudaFuncAttributeMaxDynamicSharedMemorySize, smem_bytes);
    dim3 grid(GRIDX, B);
    clustered_attn_kernel<<<grid, NTHREADS, smem_bytes>>>(Q, K, V, Out);
}

// round 13
// speedup vs baseline: 1.7556x; 1.4277x over previous
#include <cuda_runtime.h>
#include <math.h>

// ClusteredAttention: b=4, l=4096, d=64 fp32, labels in [0,8).
// Counting-sort by label (coalesced strided loads, deterministic (tid,k)
// order, predicated register histogram) -> perm/slab/block-table; gather K/V
// cluster-contiguous with tf32 pre-conversion; flash-attend cluster-aligned
// 64-query blocks with m16n8k8 TF32 MMAs (PADS=68 -> conflict-free operand
// LDS; Q fragments hoisted to registers). Time-query split-softmax absorbed
// into spare grid slots; combine fused into last chunk block.

#define LSEQ 4096
#define LM1  4095
#define HD   64
#define BM   64
#define BN   64
#define PADS 68
#define NTHREADS 256
#define MAXB 4
#define MAXBLK 72
#define TQ_CHUNKS 256
#define TQ_NCH    (LSEQ / TQ_CHUNKS)   // 16
#define GRIDX     (MAXBLK + TQ_NCH)    // 88

__device__ float g_Ks[MAXB * LSEQ * HD];   // tf32-rounded
__device__ float g_Vs[MAXB * LSEQ * HD];   // tf32-rounded
__device__ int   g_perm[MAXB * LSEQ];
__device__ int   g_slab[MAXB * LSEQ];
__device__ int4  g_btab[MAXB * MAXBLK];
__device__ int   g_nblk[MAXB];
__device__ float g_tq[MAXB * TQ_NCH * (HD + 2)];
__device__ int   g_tqcnt[MAXB];

__device__ __forceinline__ unsigned f2tf32(float v) {
    unsigned r;
    asm("cvt.rna.tf32.f32 %0, %1;" : "=r"(r) : "f"(v));
    return r;
}

__device__ __forceinline__ void mma_tf32(float c[4],
                                         unsigned a0, unsigned a1,
                                         unsigned a2, unsigned a3,
                                         unsigned b0, unsigned b1) {
    asm("mma.sync.aligned.m16n8k8.row.col.f32.tf32.tf32.f32 "
        "{%0,%1,%2,%3}, {%4,%5,%6,%7}, {%8,%9}, {%0,%1,%2,%3};"
        : "+f"(c[0]), "+f"(c[1]), "+f"(c[2]), "+f"(c[3])
        : "r"(a0), "r"(a1), "r"(a2), "r"(a3), "r"(b0), "r"(b1));
}

// ---------------------------------------------------------------------------
// Kernel A: counting sort. Coalesced strided label loads; deterministic
// (tid,k)-lexicographic ordering; no local-memory arrays.
// ---------------------------------------------------------------------------
__global__ void sort_kernel(const int* __restrict__ lab32)
{
    __shared__ int cnt[8][256];
    __shared__ int ex[8][256];
    __shared__ int tot[8];
    __shared__ int segstart[8];
    __shared__ int sh_is64;

    const int b = blockIdx.x;
    const int tid = threadIdx.x;

    if (tid < 32) {
        int nz = (lab32[2 * tid + 1] != 0) ? 1 : 0;
        unsigned any = __ballot_sync(0xffffffffu, nz);
        if (tid == 0) { sh_is64 = (any == 0u); g_tqcnt[b] = 0; }
    }
    __syncthreads();
    const int is64 = sh_is64;
    const int labbase = b * LM1;

    // coalesced: element (tid,k) = original index k*256 + tid
    int mylab[16];
    int lh[8] = {0, 0, 0, 0, 0, 0, 0, 0};
    #pragma unroll
    for (int k = 0; k < 16; k++) {
        int i = k * 256 + tid;
        int l = -1;
        if (i < LM1) {
            int gi = labbase + i;
            l = lab32[is64 ? (2 * gi) : gi];
        }
        mylab[k] = l;
        #pragma unroll
        for (int c = 0; c < 8; c++) lh[c] += (l == c);
    }
    #pragma unroll
    for (int l = 0; l < 8; l++) cnt[l][tid] = lh[l];
    __syncthreads();

    {
        int w = tid >> 5, lane = tid & 31;
        int carry = 0;
        for (int c = 0; c < 8; c++) {
            int t = c * 32 + lane;
            int v = cnt[w][t];
            int x = v;
            #pragma unroll
            for (int o = 1; o < 32; o <<= 1) {
                int y = __shfl_up_sync(0xffffffffu, x, o);
                if (lane >= o) x += y;
            }
            ex[w][t] = carry + x - v;
            carry += __shfl_sync(0xffffffffu, x, 31);
        }
        if (lane == 0) tot[w] = carry;
    }
    __syncthreads();

    if (tid == 0) {
        int s = 0;
        int nb = 0;
        #pragma unroll
        for (int l = 0; l < 8; l++) {
            segstart[l] = s;
            int e = s + tot[l];
            int kb = s & ~(BN - 1);
            int ke = min((e + BN - 1) & ~(BN - 1), LSEQ);
            for (int q0 = s; q0 < e; q0 += BM) {
                g_btab[b * MAXBLK + nb] = make_int4(q0, e, kb, ke);
                nb++;
            }
            s = e;
        }
        g_nblk[b] = nb;
        g_perm[b * LSEQ + LM1] = LM1;
        g_slab[b * LSEQ + LM1] = -2;
    }
    __syncthreads();

    // scatter in (tid,k) order; run-count via unrolled register compares
    #pragma unroll
    for (int k = 0; k < 16; k++) {
        int l = mylab[k];
        if (l >= 0) {
            int run = 0;
            #pragma unroll
            for (int k2 = 0; k2 < 16; k2++)
                if (k2 < k) run += (mylab[k2] == l);
            int pos = segstart[l] + ex[l][tid] + run;
            g_perm[b * LSEQ + pos] = k * 256 + tid;
            g_slab[b * LSEQ + pos] = l;
        }
    }
}

// ---------------------------------------------------------------------------
// Kernel B: gather K/V rows into sorted order + tf32 pre-conversion.
// ---------------------------------------------------------------------------
__global__ void gather_kernel(const float* __restrict__ K,
                              const float* __restrict__ V)
{
    int idx = blockIdx.x * blockDim.x + threadIdx.x;
    int r = idx >> 4;
    int c = idx & 15;
    int b = r >> 12;
    int src = g_perm[r];
    long long so = ((long long)(b << 12) + src) * 16 + c;
    float4 k4 = ((const float4*)K)[so];
    float4 v4 = ((const float4*)V)[so];
    k4.x = __uint_as_float(f2tf32(k4.x));
    k4.y = __uint_as_float(f2tf32(k4.y));
    k4.z = __uint_as_float(f2tf32(k4.z));
    k4.w = __uint_as_float(f2tf32(k4.w));
    v4.x = __uint_as_float(f2tf32(v4.x));
    v4.y = __uint_as_float(f2tf32(v4.y));
    v4.z = __uint_as_float(f2tf32(v4.z));
    v4.w = __uint_as_float(f2tf32(v4.w));
    ((float4*)g_Ks)[r * 16 + c] = k4;
    ((float4*)g_Vs)[r * 16 + c] = v4;
}

// ---------------------------------------------------------------------------
// Kernel C: main kernel, 256 threads, TF32 tensor-core GEMMs.
// ---------------------------------------------------------------------------
__global__ __launch_bounds__(NTHREADS, 2)
void clustered_attn_kernel(const float* __restrict__ Q,
                           const float* __restrict__ K,
                           const float* __restrict__ V,
                           float* __restrict__ Out)
{
    extern __shared__ float sm[];

    const int b    = blockIdx.y;
    const int slot = blockIdx.x;
    const int tid  = threadIdx.x;
    const int nblk = g_nblk[b];
    const long long bbase = (long long)b * LSEQ;
    const float scale = 0.125f;

    // ===================== time-query chunk path (exact fp32) ============
    if (slot >= nblk) {
        const int c = slot - nblk;
        if (c >= TQ_NCH) return;

        float* q    = sm;
        float* p    = sm + 64;
        float* red  = sm + 320;
        float* vacc = sm + 336;
        __shared__ int amlast;

        if (tid < HD) q[tid] = Q[(bbase + LM1) * HD + tid];
        __syncthreads();

        const int j = c * TQ_CHUNKS + tid;
        const float* kr = K + (bbase + j) * HD;
        float dot = 0.0f;
        #pragma unroll
        for (int d = 0; d < HD; d += 4) {
            float4 k4 = *reinterpret_cast<const float4*>(kr + d);
            dot += q[d] * k4.x + q[d + 1] * k4.y + q[d + 2] * k4.z + q[d + 3] * k4.w;
        }
        dot *= scale;

        float m = dot;
        #pragma unroll
        for (int o = 16; o >= 1; o >>= 1)
            m = fmaxf(m, __shfl_xor_sync(0xffffffffu, m, o));
        if ((tid & 31) == 0) red[tid >> 5] = m;
        __syncthreads();
        m = red[0];
        #pragma unroll
        for (int w = 1; w < 8; w++) m = fmaxf(m, red[w]);

        float pv = __expf(dot - m);
        p[tid] = pv;

        float s = pv;
        #pragma unroll
        for (int o = 16; o >= 1; o >>= 1)
            s += __shfl_xor_sync(0xffffffffu, s, o);
        if ((tid & 31) == 0) red[8 + (tid >> 5)] = s;
        __syncthreads();
        s = red[8];
        #pragma unroll
        for (int w = 1; w < 8; w++) s += red[8 + w];

        const int d = tid & 63, h = tid >> 6;
        float a = 0.0f;
        #pragma unroll 8
        for (int jj = h * 64; jj < h * 64 + 64; jj++)
            a += p[jj] * V[(bbase + c * TQ_CHUNKS + jj) * HD + d];
        vacc[h * HD + d] = a;
        __syncthreads();

        float* out = g_tq + (b * TQ_NCH + c) * (HD + 2);
        if (tid < HD)
            out[tid] = vacc[tid] + vacc[HD + tid] + vacc[2 * HD + tid] + vacc[3 * HD + tid];
        else if (tid == HD) { out[HD] = m; out[HD + 1] = s; }
        __syncthreads();

        __threadfence();
        if (tid == 0) amlast = (atomicAdd(&g_tqcnt[b], 1) == TQ_NCH - 1);
        __syncthreads();
        if (!amlast) return;
        __threadfence();

        if (tid < HD) {
            const float* part = g_tq + b * TQ_NCH * (HD + 2);
            float M = -INFINITY;
            #pragma unroll
            for (int cc = 0; cc < TQ_NCH; cc++)
                M = fmaxf(M, part[cc * (HD + 2) + HD]);
            float stot = 0.0f, a2 = 0.0f;
            #pragma unroll
            for (int cc = 0; cc < TQ_NCH; cc++) {
                float f = __expf(part[cc * (HD + 2) + HD] - M);
                stot += part[cc * (HD + 2) + HD + 1] * f;
                a2   += part[cc * (HD + 2) + tid] * f;
            }
            Out[(bbase + LM1) * HD + tid] = a2 / stot;
        }
        return;
    }

    // ===================== attention path =====================
    float* Qs = sm;                      // [64][PADS] row-major, scaled tf32
    float* Ks = Qs + 64 * PADS;          // [64][PADS] tf32
    float* Vs = Ks + 64 * PADS;          // [64][PADS] tf32
    float* St = Vs + 64 * PADS;          // [64][PADS] scores / probs
    float* kt = St + 64 * PADS;          // [64] exact time key
    float* vt = kt + 64;                 // [64] exact time value
    float* frow_s = vt + 64;             // [64] per-row rescale
    float* ft_s   = frow_s + 64;
    float* pt_s   = ft_s + 64;
    float* li_s   = pt_s + 64;
    int*   klabs  = (int*)(li_s + 64);   // [64]

    const unsigned* Qu = (const unsigned*)Qs;
    const unsigned* Ku = (const unsigned*)Ks;
    const unsigned* Vu = (const unsigned*)Vs;
    const unsigned* Su = (const unsigned*)St;

    const int4 blk = g_btab[b * MAXBLK + slot];
    const int q0 = blk.x, qe = blk.y, kb = blk.z, ke = blk.w;

    const int tx = tid & 15;
    const int ty = tid >> 4;
    const int lane = tid & 31;
    const int warp = tid >> 5;
    const int mw = 16 * (warp >> 1);     // warp's m-slab (0/16/32/48)
    const int nw = 32 * (warp & 1);      // warp's n-half (0/32)
    const int gid = lane >> 2;
    const int tig = lane & 3;
    const int rA0 = (mw + gid) * PADS;
    const int rA1 = (mw + gid + 8) * PADS;

    const int* perm = g_perm + b * LSEQ;
    const int* slab = g_slab + b * LSEQ;
    const float* Kb = g_Ks + b * LSEQ * HD;
    const float* Vb = g_Vs + b * LSEQ * HD;

    // ---- stage Q (row-major, scaled, tf32) + exact time K/V
    #pragma unroll
    for (int idx = tid; idx < BM * HD; idx += NTHREADS) {
        int m = idx >> 6, d = idx & 63;
        int src = perm[min(q0 + m, LM1)];
        float v = Q[(bbase + src) * HD + d] * scale;
        Qs[m * PADS + d] = __uint_as_float(f2tf32(v));
    }
    if (tid < HD) kt[tid] = K[(bbase + LM1) * HD + tid];
    else if (tid < 2 * HD) vt[tid - HD] = V[(bbase + LM1) * HD + (tid - HD)];
    __syncthreads();

    // ---- hoist Q fragments (tile-invariant) into registers
    unsigned aq[8][4];
    #pragma unroll
    for (int kg = 0; kg < 8; kg++) {
        int k0 = kg * 8;
        aq[kg][0] = Qu[rA0 + k0 + tig];
        aq[kg][1] = Qu[rA1 + k0 + tig];
        aq[kg][2] = Qu[rA0 + k0 + tig + 4];
        aq[kg][3] = Qu[rA1 + k0 + tig + 4];
    }

    int qlab[4];
    #pragma unroll
    for (int i = 0; i < 4; i++) {
        int r = q0 + ty * 4 + i;
        qlab[i] = (r < qe) ? slab[r] : -3;
    }

    float mrow[4], lrow[4];
    #pragma unroll
    for (int i = 0; i < 4; i++) { mrow[i] = -INFINITY; lrow[i] = 0.0f; }

    float oc[4][4];
    #pragma unroll
    for (int ng = 0; ng < 4; ng++)
        #pragma unroll
        for (int r = 0; r < 4; r++) oc[ng][r] = 0.0f;

    for (int n0 = kb; n0 < ke; n0 += BN) {
        __syncthreads();   // prev PV reads done

        // ---- stage K/V tiles (row-major float2 copy; already tf32)
        #pragma unroll
        for (int idx = tid; idx < BN * 32; idx += NTHREADS) {
            int n = idx >> 5, c = (idx & 31) * 2;
            *(float2*)&Ks[n * PADS + c] = *(const float2*)&Kb[(n0 + n) * HD + c];
            *(float2*)&Vs[n * PADS + c] = *(const float2*)&Vb[(n0 + n) * HD + c];
        }
        if (tid < BN) klabs[tid] = slab[n0 + tid];
        __syncthreads();

        // ---- S = Q K^T via tensor cores (conflict-free B loads, PADS=68)
        float sc[4][4];
        #pragma unroll
        for (int ng = 0; ng < 4; ng++)
            #pragma unroll
            for (int r = 0; r < 4; r++) sc[ng][r] = 0.0f;

        #pragma unroll
        for (int kg = 0; kg < 8; kg++) {
            int k0 = kg * 8;
            #pragma unroll
            for (int ng = 0; ng < 4; ng++) {
                int nb = (nw + 8 * ng + gid) * PADS + k0 + tig;
                mma_tf32(sc[ng], aq[kg][0], aq[kg][1], aq[kg][2], aq[kg][3],
                         Ku[nb], Ku[nb + 4]);
            }
        }
        #pragma unroll
        for (int ng = 0; ng < 4; ng++) {
            int cbase = nw + 8 * ng + 2 * tig;
            *(float2*)&St[rA0 + cbase] = make_float2(sc[ng][0], sc[ng][1]);
            *(float2*)&St[rA1 + cbase] = make_float2(sc[ng][2], sc[ng][3]);
        }
        __syncthreads();

        // ---- mask + online softmax (scalar path on smem S)
        int klj[4];
        #pragma unroll
        for (int j = 0; j < 4; j++) klj[j] = klabs[4 * tx + j];

        #pragma unroll
        for (int i = 0; i < 4; i++) {
            int rbase = (4 * ty + i) * PADS + 4 * tx;
            float2 lo = *(const float2*)&St[rbase];
            float2 hi = *(const float2*)&St[rbase + 2];
            float s0 = (qlab[i] == klj[0]) ? lo.x : -INFINITY;
            float s1 = (qlab[i] == klj[1]) ? lo.y : -INFINITY;
            float s2 = (qlab[i] == klj[2]) ? hi.x : -INFINITY;
            float s3 = (qlab[i] == klj[3]) ? hi.y : -INFINITY;

            float tm = fmaxf(fmaxf(s0, s1), fmaxf(s2, s3));
            #pragma unroll
            for (int o = 8; o >= 1; o >>= 1)
                tm = fmaxf(tm, __shfl_xor_sync(0xffffffffu, tm, o));

            float newm = fmaxf(mrow[i], tm);
            float mref = (newm == -INFINITY) ? 0.0f : newm;
            float fi = __expf(mrow[i] - mref);

            float p0 = __expf(s0 - mref);
            float p1 = __expf(s1 - mref);
            float p2 = __expf(s2 - mref);
            float p3 = __expf(s3 - mref);
            float rs = (p0 + p1) + (p2 + p3);
            #pragma unroll
            for (int o = 8; o >= 1; o >>= 1)
                rs += __shfl_xor_sync(0xffffffffu, rs, o);

            lrow[i] = lrow[i] * fi + rs;
            mrow[i] = newm;

            *(float2*)&St[rbase] = make_float2(__uint_as_float(f2tf32(p0)),
                                               __uint_as_float(f2tf32(p1)));
            *(float2*)&St[rbase + 2] = make_float2(__uint_as_float(f2tf32(p2)),
                                                   __uint_as_float(f2tf32(p3)));
            if (tx == 0) frow_s[4 * ty + i] = fi;
        }
        __syncthreads();

        // ---- O = O*f + P V via tensor cores (conflict-free V loads)
        {
            float f0 = frow_s[mw + gid];
            float f1 = frow_s[mw + gid + 8];
            #pragma unroll
            for (int ng = 0; ng < 4; ng++) {
                oc[ng][0] *= f0; oc[ng][1] *= f0;
                oc[ng][2] *= f1; oc[ng][3] *= f1;
            }
        }
        #pragma unroll
        for (int kg = 0; kg < 8; kg++) {
            int k0 = kg * 8;
            unsigned a0 = Su[rA0 + k0 + tig];
            unsigned a1 = Su[rA1 + k0 + tig];
            unsigned a2 = Su[rA0 + k0 + tig + 4];
            unsigned a3 = Su[rA1 + k0 + tig + 4];
            #pragma unroll
            for (int ng = 0; ng < 4; ng++) {
                int vb = (k0 + tig) * PADS + nw + 8 * ng + gid;
                mma_tf32(oc[ng], a0, a1, a2, a3, Vu[vb], Vu[vb + 4 * PADS]);
            }
        }
    }

    // ---- time key column (exact fp32)
    #pragma unroll
    for (int i = 0; i < 4; i++) {
        int row = 4 * ty + i;
        float part = 0.0f;
        #pragma unroll
        for (int jj = 0; jj < 4; jj++)
            part += Qs[row * PADS + 4 * tx + jj] * kt[4 * tx + jj];
        #pragma unroll
        for (int o = 8; o >= 1; o >>= 1)
            part += __shfl_xor_sync(0xffffffffu, part, o);
        float st = part;   // Q pre-scaled

        float newm = fmaxf(mrow[i], st);
        float f = __expf(mrow[i] - newm);
        float p = __expf(st - newm);
        lrow[i] = lrow[i] * f + p;
        mrow[i] = newm;
        if (tx == 0) {
            ft_s[row] = f;
            pt_s[row] = p;
            li_s[row] = 1.0f / lrow[i];
        }
    }
    __syncthreads();

    // ---- epilogue on O frags: time-key add, normalize, scatter
    {
        float f0 = ft_s[mw + gid],     p0 = pt_s[mw + gid],     i0 = li_s[mw + gid];
        float f1 = ft_s[mw + gid + 8], p1 = pt_s[mw + gid + 8], i1 = li_s[mw + gid + 8];
        int r0 = q0 + mw + gid;
        int r1 = r0 + 8;
        bool good0 = r0 < qe, good1 = r1 < qe;
        long long o0 = good0 ? (bbase + perm[r0]) * HD : 0;
        long long o1 = good1 ? (bbase + perm[r1]) * HD : 0;

        #pragma unroll
        for (int ng = 0; ng < 4; ng++) {
            int col = nw + 8 * ng + 2 * tig;
            float x0 = (oc[ng][0] * f0 + p0 * vt[col])     * i0;
            float x1 = (oc[ng][1] * f0 + p0 * vt[col + 1]) * i0;
            float x2 = (oc[ng][2] * f1 + p1 * vt[col])     * i1;
            float x3 = (oc[ng][3] * f1 + p1 * vt[col + 1]) * i1;
            if (good0) *(float2*)&Out[o0 + col] = make_float2(x0, x1);
            if (good1) *(float2*)&Out[o1 + col] = make_float2(x2, x3);
        }
    }
}

// ---------------------------------------------------------------------------
extern "C" void kernel_launch(void* const* d_in, const int* in_sizes, int n_in,
                              void* d_out, int out_size)
{
    const float* Q = (const float*)d_in[0];
    const float* K = (const float*)d_in[1];
    const float* V = (const float*)d_in[2];
    const int* lab = (const int*)d_in[3];
    float* Out = (float*)d_out;

    const int B = in_sizes[0] / (LSEQ * HD);

    sort_kernel<<<B, 256>>>(lab);
    gather_kernel<<<B * 256, 256>>>(K, V);

    const int smem_bytes = (4 * 64 * PADS + 7 * 64) * (int)sizeof(float)
                           + 64 * (int)sizeof(int);
    cudaFuncSetAttribute(clustered_attn_kernel,
                         cudaFuncAttributeMaxDynamicSharedMemorySize, smem_bytes);
    dim3 grid(GRIDX, B);
    clustered_attn_kernel<<<grid, NTHREADS, smem_bytes>>>(Q, K, V, Out);
}